// round 15
// baseline (speedup 1.0000x reference)
#include <cuda_runtime.h>

// LSTMBrain: 2-layer LSTM (hidden=3) over [B=4096, T=2048], dense head 3->1.
// Round 15: layer-per-lane (R12) rebuilt. Even lane = full L1 of element e,
// odd lane = full L2; recurrences fully IN-REGISTER (no exchange in chain);
// s1 handoff L1->L2 via 3 shfl_up (consumed next step -> off-chain).
// Fixes vs R12 (396 cyc/step):
//  - STEP written STAGE-MAJOR: z trees | 12 gate ex2 (f first) | adds/muls |
//    3 Rm rcps | cell updates | 3 cell ex2 | ONE paired Rq rcp | outputs.
//    The three unit cascades are independent -> interleaved issue fills the
//    MUFU rt-8 gaps and latencies (R12 serialized them).
//  - z matvec tree'd (two 3-deep ffma2 halves + fadd2).
//  - Rq paired across the 3 units: 19 MUFU/step (was 21).
// 16 elements per warp -> best MUFU-instr/element of any partition (1.19).

typedef unsigned long long u64;

#define FULLM 0xFFFFFFFFu
#define LOG2E 1.4426950408889634f

__device__ __forceinline__ float fast_rcp(float x) {
    float r; asm("rcp.approx.f32 %0, %1;" : "=f"(r) : "f"(x)); return r;
}
__device__ __forceinline__ float fast_ex2(float x) {
    float r; asm("ex2.approx.f32 %0, %1;" : "=f"(r) : "f"(x)); return r;
}
__device__ __forceinline__ u64 ffma2(u64 a, u64 b, u64 c) {
    u64 d; asm("fma.rn.f32x2 %0, %1, %2, %3;" : "=l"(d) : "l"(a), "l"(b), "l"(c));
    return d;
}
__device__ __forceinline__ u64 fmul2(u64 a, u64 b) {
    u64 d; asm("mul.rn.f32x2 %0, %1, %2;" : "=l"(d) : "l"(a), "l"(b)); return d;
}
__device__ __forceinline__ u64 fadd2(u64 a, u64 b) {
    u64 d; asm("add.rn.f32x2 %0, %1, %2;" : "=l"(d) : "l"(a), "l"(b)); return d;
}
__device__ __forceinline__ u64 pack2(float lo, float hi) {
    u64 d; asm("mov.b64 %0, {%1, %2};" : "=l"(d) : "f"(lo), "f"(hi)); return d;
}
__device__ __forceinline__ void unpack2(u64 v, float& lo, float& hi) {
    asm("mov.b64 {%0, %1}, %2;" : "=f"(lo), "=f"(hi) : "l"(v));
}

__global__ void __launch_bounds__(64, 1) lstm2_r15_kernel(
    const float* __restrict__ state,
    const float* __restrict__ W1, const float* __restrict__ U1, const float* __restrict__ b1,
    const float* __restrict__ W2, const float* __restrict__ U2, const float* __restrict__ b2,
    const float* __restrict__ Wd, const float* __restrict__ bd,
    float* __restrict__ out, int B, int T)
{
    const int tid  = blockIdx.x * 64 + threadIdx.x;
    const bool isL2 = (tid & 1) != 0;
    int e = tid >> 1;                      // element of this lane pair
    const bool act = (e < B);
    if (!act) e = B - 1;

    // ---- coefficients: j = u*2 + pr; pr 0 -> gates (i,f), pr 1 -> (g,o)
    // column(gate) = gate*3 + u; sigma scale -log2e, tanh gate -2log2e.
    u64 CB0[6], CB1[6], CB2[6], CC0[6], CC1[6], CC2[6], BI[6];
#pragma unroll
    for (int u = 0; u < 3; ++u) {
#pragma unroll
        for (int pr = 0; pr < 2; ++pr) {
            const int j   = u * 2 + pr;
            const int glo = pr ? 2 : 0, ghi = pr ? 3 : 1;
            const int clo = glo * 3 + u, chi = ghi * 3 + u;
            const float slo = pr ? (-2.0f * LOG2E) : (-LOG2E);
            const float shi = -LOG2E;
            if (isL2) {
                BI[j]  = pack2(__ldg(b2 + clo) * slo, __ldg(b2 + chi) * shi);
                CB0[j] = pack2(__ldg(W2 + 0 * 12 + clo) * slo, __ldg(W2 + 0 * 12 + chi) * shi);
                CB1[j] = pack2(__ldg(W2 + 1 * 12 + clo) * slo, __ldg(W2 + 1 * 12 + chi) * shi);
                CB2[j] = pack2(__ldg(W2 + 2 * 12 + clo) * slo, __ldg(W2 + 2 * 12 + chi) * shi);
                CC0[j] = pack2(__ldg(U2 + 0 * 12 + clo) * slo, __ldg(U2 + 0 * 12 + chi) * shi);
                CC1[j] = pack2(__ldg(U2 + 1 * 12 + clo) * slo, __ldg(U2 + 1 * 12 + chi) * shi);
                CC2[j] = pack2(__ldg(U2 + 2 * 12 + clo) * slo, __ldg(U2 + 2 * 12 + chi) * shi);
            } else {
                BI[j]  = pack2(__ldg(b1 + clo) * slo, __ldg(b1 + chi) * shi);
                CB0[j] = pack2(__ldg(W1 + clo) * slo, __ldg(W1 + chi) * shi);  // * x
                CB1[j] = 0; CB2[j] = 0;
                CC0[j] = pack2(__ldg(U1 + 0 * 12 + clo) * slo, __ldg(U1 + 0 * 12 + chi) * shi);
                CC1[j] = pack2(__ldg(U1 + 1 * 12 + clo) * slo, __ldg(U1 + 1 * 12 + chi) * shi);
                CC2[j] = pack2(__ldg(U1 + 2 * 12 + clo) * slo, __ldg(U1 + 2 * 12 + chi) * shi);
            }
        }
    }

    const float* xrow = state + (size_t)e * (size_t)T;

    u64 O0 = 0, O1 = 0, O2 = 0;           // own-layer hidden (dup u64)
    u64 R0 = 0, R1 = 0, R2 = 0;           // received s1 (dup u64, L2 only)
    float cc0 = 0.f, cc1 = 0.f, cc2 = 0.f;
    float ov0 = 0.f, ov1 = 0.f, ov2 = 0.f;

    // STAGE-MAJOR step: all three unit cascades interleaved.
#define STEP(xv)                                                            \
    do {                                                                    \
        const u64 R0e = isL2 ? R0 : pack2((xv), (xv));                      \
        /* stage Z: 6 tree'd gate-pair matvecs */                           \
        u64 z[6];                                                           \
        _Pragma("unroll")                                                   \
        for (int j = 0; j < 6; ++j) {                                       \
            u64 t1 = ffma2(CB1[j], R1, ffma2(CB0[j], R0e, BI[j]));          \
            t1 = ffma2(CB2[j], R2, t1);                                     \
            u64 t2 = ffma2(CC1[j], O1, fmul2(CC0[j], O0));                  \
            t2 = ffma2(CC2[j], O2, t2);                                     \
            z[j] = fadd2(t1, t2);                                           \
        }                                                                   \
        /* stage E: gate exponentials, f-gates first (chain-critical) */    \
        float zi0, zf0, zi1, zf1, zi2, zf2;                                 \
        unpack2(z[0], zi0, zf0); unpack2(z[2], zi1, zf1);                   \
        unpack2(z[4], zi2, zf2);                                            \
        const float ef0 = fast_ex2(zf0);                                    \
        const float ef1 = fast_ex2(zf1);                                    \
        const float ef2 = fast_ex2(zf2);                                    \
        const float ei0 = fast_ex2(zi0);                                    \
        const float ei1 = fast_ex2(zi1);                                    \
        const float ei2 = fast_ex2(zi2);                                    \
        float zg0, zo0, zg1, zo1, zg2, zo2;                                 \
        unpack2(z[1], zg0, zo0); unpack2(z[3], zg1, zo1);                   \
        unpack2(z[5], zg2, zo2);                                            \
        const float eg0 = fast_ex2(zg0);                                    \
        const float eg1 = fast_ex2(zg1);                                    \
        const float eg2 = fast_ex2(zg2);                                    \
        const float eo0 = fast_ex2(zo0);                                    \
        const float eo1 = fast_ex2(zo1);                                    \
        const float eo2 = fast_ex2(zo2);                                    \
        /* stage D: denominators + products (fills MUFU latency) */         \
        const float df0 = 1.0f + ef0, df1 = 1.0f + ef1, df2 = 1.0f + ef2;   \
        const float di0 = 1.0f + ei0, di1 = 1.0f + ei1, di2 = 1.0f + ei2;   \
        const float dg0 = 1.0f + eg0, dg1 = 1.0f + eg1, dg2 = 1.0f + eg2;   \
        const float dq0 = 1.0f + eo0, dq1 = 1.0f + eo1, dq2 = 1.0f + eo2;   \
        const float m0 = di0 * dg0, m1 = di1 * dg1, m2 = di2 * dg2;         \
        const float t0 = m0 * df0,  t1 = m1 * df1,  t2 = m2 * df2;          \
        /* stage R: per-unit triple rcp */                                  \
        const float Rm0 = fast_rcp(t0);                                     \
        const float Rm1 = fast_rcp(t1);                                     \
        const float Rm2 = fast_rcp(t2);                                     \
        const float pp0 = fmaf(2.0f * LOG2E, eg0, -2.0f * LOG2E);           \
        const float pp1 = fmaf(2.0f * LOG2E, eg1, -2.0f * LOG2E);           \
        const float pp2 = fmaf(2.0f * LOG2E, eg2, -2.0f * LOG2E);           \
        /* stage C: cell updates */                                         \
        cc0 = fmaf(Rm0 * m0, cc0, pp0 * (Rm0 * df0));                       \
        cc1 = fmaf(Rm1 * m1, cc1, pp1 * (Rm1 * df1));                       \
        cc2 = fmaf(Rm2 * m2, cc2, pp2 * (Rm2 * df2));                       \
        const float ec0 = fast_ex2(cc0);                                    \
        const float ec1 = fast_ex2(cc1);                                    \
        const float ec2 = fast_ex2(cc2);                                    \
        /* stage O: paired output rcp across the 3 units */                 \
        const float q0 = (1.0f + ec0) * dq0;                                \
        const float q1 = (1.0f + ec1) * dq1;                                \
        const float q2 = (1.0f + ec2) * dq2;                                \
        const float q01 = q0 * q1, Q = q01 * q2;                            \
        const float RQ  = fast_rcp(Q);                                      \
        const float Rq2 = RQ * q01;                                         \
        const float w01 = RQ * q2;                                          \
        const float Rq0 = w01 * q1;                                         \
        const float Rq1 = w01 * q0;                                         \
        ov0 = (1.0f - ec0) * Rq0;                                           \
        ov1 = (1.0f - ec1) * Rq1;                                           \
        ov2 = (1.0f - ec2) * Rq2;                                           \
    } while (0)

    // handoff: s1 -> L2 lane (consumed next step, off the recurrence chain)
#define XFER()                                                              \
    do {                                                                    \
        const float r0 = __shfl_up_sync(FULLM, ov0, 1, 2);                  \
        const float r1 = __shfl_up_sync(FULLM, ov1, 1, 2);                  \
        const float r2 = __shfl_up_sync(FULLM, ov2, 1, 2);                  \
        O0 = pack2(ov0, ov0); O1 = pack2(ov1, ov1); O2 = pack2(ov2, ov2);   \
        R0 = pack2(r0, r0);   R1 = pack2(r1, r1);   R2 = pack2(r2, r2);     \
    } while (0)

#define BODY(xv) do { STEP(xv); XFER(); } while (0)

    // ---- prologue: iter 0. L1 produces s1(0); L2 output invalid (no
    // h2(-1)/s1(-1)) -> reset L2 state before the handoff.
    float4 a4 = __ldg(reinterpret_cast<const float4*>(xrow));
    float4 nA = a4;
    if (T >= 8) nA = __ldg(reinterpret_cast<const float4*>(xrow + 4));

    STEP(a4.x);
    if (isL2) { cc0 = cc1 = cc2 = 0.f; ov0 = ov1 = ov2 = 0.f; }
    XFER();
    BODY(a4.y);
    BODY(a4.z);
    BODY(a4.w);

    int t = 4;
    for (; t + 7 < T; t += 4) {
        a4 = nA;
        nA = __ldg(reinterpret_cast<const float4*>(xrow + t + 4));
        BODY(a4.x);
        BODY(a4.y);
        BODY(a4.z);
        BODY(a4.w);
    }
    if (t + 3 < T) {                      // last full chunk (already prefetched)
        a4 = nA;
        BODY(a4.x);
        BODY(a4.y);
        BODY(a4.z);
        BODY(a4.w);
        t += 4;
    }
    for (; t < T; ++t) {                  // scalar tail (not taken for T=2048)
        BODY(__ldg(xrow + t));
    }

    // ---- epilogue: one more iter so L2 lanes produce h2(T-1) from s1(T-1).
    // L1 lanes compute garbage (x = 0), never consumed.
    STEP(0.0f);

    if (isL2 && act) {
        float r = __ldg(bd);
        r = fmaf(ov0, __ldg(Wd + 0), r);
        r = fmaf(ov1, __ldg(Wd + 1), r);
        r = fmaf(ov2, __ldg(Wd + 2), r);
        out[e] = r;
    }

#undef STEP
#undef XFER
#undef BODY
}

extern "C" void kernel_launch(void* const* d_in, const int* in_sizes, int n_in,
                              void* d_out, int out_size)
{
    const float* state = (const float*)d_in[0];
    const float* W1 = (const float*)d_in[1];
    const float* U1 = (const float*)d_in[2];
    const float* b1 = (const float*)d_in[3];
    const float* W2 = (const float*)d_in[4];
    const float* U2 = (const float*)d_in[5];
    const float* b2 = (const float*)d_in[6];
    const float* Wd = (const float*)d_in[7];
    const float* bd = (const float*)d_in[8];
    float* out = (float*)d_out;

    const int B = out_size;            // output is [1, B]
    const int T = in_sizes[0] / B;     // state is [B, T]

    const int elems_per_block = 32;    // 64 threads = 32 lane pairs
    const int blocks = (B + elems_per_block - 1) / elems_per_block;  // 128
    lstm2_r15_kernel<<<blocks, 64>>>(state, W1, U1, b1, W2, U2, b2,
                                     Wd, bd, out, B, T);
}

// round 16
// speedup vs baseline: 1.1489x; 1.1489x over previous
#include <cuda_runtime.h>

// LSTMBrain: 2-layer LSTM (hidden=3) over [B=4096, T=2048], dense head 3->1.
// Round 16: R9 layout/exchange verbatim; activations re-engineered:
//   sigma(z) = 0.5 + 0.5*t(z/2), t = tanh continued-fraction convergent
//     t(x) = x*(10395+1260y+21y^2)/(10395+4725y+210y^2+y^3), y = x^2
//   (verified: err <=1e-6 for |x|<=1.3, ~1e-5 at x=2.0).
//   i,f: packed f32x2 rational (weights pre-scaled 0.5; 0.5*N folded).
//   o:   scalar rational (weights pre-scaled 0.5).
//   g:   ex2 route (weights pre-scaled -2*log2e), cell kept in -2L*c domain.
//   MUFU/step: 4 (ex2 g, rcp(di*df*dg), ex2 cc, rcp(dc*den_o)) vs R9's 7.
// 8 lanes/element (0-2 L1 units, 4-6 L2 units, 3/7 dup), 4 elems/warp,
// 1024 warps; smem exchange STS.64 dup + syncwarp + 3x LDS.128 (R9).

typedef unsigned long long u64;

#define FULLM 0xFFFFFFFFu
#define LOG2E 1.4426950408889634f

__device__ __forceinline__ float fast_rcp(float x) {
    float r; asm("rcp.approx.f32 %0, %1;" : "=f"(r) : "f"(x)); return r;
}
__device__ __forceinline__ float fast_ex2(float x) {
    float r; asm("ex2.approx.f32 %0, %1;" : "=f"(r) : "f"(x)); return r;
}
__device__ __forceinline__ u64 ffma2(u64 a, u64 b, u64 c) {
    u64 d; asm("fma.rn.f32x2 %0, %1, %2, %3;" : "=l"(d) : "l"(a), "l"(b), "l"(c));
    return d;
}
__device__ __forceinline__ u64 fmul2(u64 a, u64 b) {
    u64 d; asm("mul.rn.f32x2 %0, %1, %2;" : "=l"(d) : "l"(a), "l"(b)); return d;
}
__device__ __forceinline__ u64 fadd2(u64 a, u64 b) {
    u64 d; asm("add.rn.f32x2 %0, %1, %2;" : "=l"(d) : "l"(a), "l"(b)); return d;
}
__device__ __forceinline__ u64 pack2(float lo, float hi) {
    u64 d; asm("mov.b64 %0, {%1, %2};" : "=l"(d) : "f"(lo), "f"(hi)); return d;
}
__device__ __forceinline__ void unpack2(u64 v, float& lo, float& hi) {
    asm("mov.b64 {%0, %1}, %2;" : "=f"(lo), "=f"(hi) : "l"(v));
}

__global__ void __launch_bounds__(32, 1) lstm2_r16_kernel(
    const float* __restrict__ state,
    const float* __restrict__ W1, const float* __restrict__ U1, const float* __restrict__ b1,
    const float* __restrict__ W2, const float* __restrict__ U2, const float* __restrict__ b2,
    const float* __restrict__ Wd, const float* __restrict__ bd,
    float* __restrict__ out, int B, int T)
{
    __shared__ __align__(16) u64 xch[2][32];   // [buffer][slot], (v,v) dup

    const int lane  = threadIdx.x & 31;
    const int lane8 = lane & 7;
    const int gbase = lane & ~7;               // group's first lane/slot
    const int sub   = lane8 & 3;
    const int u     = (sub < 3) ? sub : 2;     // owned hidden unit (3/7 dup 2)
    const bool isL2 = (lane8 & 4) != 0;
    // permuted write slot: roles 0,1,2 -> 0,1,2 ; 4,5,6 -> 3,4,5 ; 3->6, 7->7
    const int sslot = gbase + ((lane8 < 3) ? lane8
                        : (lane8 == 3) ? 6
                        : (lane8 < 7) ? (lane8 - 1) : 7);

    int e = blockIdx.x * 4 + (lane >> 3);      // element of this group
    const bool act = (e < B);
    if (!act) e = B - 1;

    // ---- gate-pair packed coefficients ----
    // pair 0 = gates (i, f): both halves pre-scaled 0.5 (rational-sigma arg z/2)
    // pair 1 = gates (g, o): g half scaled -2*log2e (ex2 route), o half 0.5
    u64 AP[2], BIP[2], BP[3][2], CP[3][2];
#pragma unroll
    for (int pr = 0; pr < 2; ++pr) {
        const int glo = (pr == 0) ? 0 : 2;     // i or g
        const int ghi = (pr == 0) ? 1 : 3;     // f or o
        const int clo = glo * 3 + u, chi = ghi * 3 + u;
        const float slo = (pr == 0) ? 0.5f : (-2.0f * LOG2E);
        const float shi = 0.5f;
        if (isL2) {
            AP[pr]  = 0;
            BIP[pr] = pack2(__ldg(b2 + clo) * slo, __ldg(b2 + chi) * shi);
#pragma unroll
            for (int k = 0; k < 3; ++k) {
                BP[k][pr] = pack2(__ldg(W2 + k * 12 + clo) * slo,
                                  __ldg(W2 + k * 12 + chi) * shi);  // * s1
                CP[k][pr] = pack2(__ldg(U2 + k * 12 + clo) * slo,
                                  __ldg(U2 + k * 12 + chi) * shi);  // * h2
            }
        } else {
            AP[pr]  = pack2(__ldg(W1 + clo) * slo, __ldg(W1 + chi) * shi);
            BIP[pr] = pack2(__ldg(b1 + clo) * slo, __ldg(b1 + chi) * shi);
#pragma unroll
            for (int k = 0; k < 3; ++k) {
                BP[k][pr] = pack2(__ldg(U1 + k * 12 + clo) * slo,
                                  __ldg(U1 + k * 12 + chi) * shi);  // * s1
                CP[k][pr] = 0;
            }
        }
    }

    // packed rational constants (numerator folded with the 0.5 of sigma)
    const u64 C_N2 = pack2(10.5f,   10.5f);
    const u64 C_N1 = pack2(630.0f,  630.0f);
    const u64 C_N0 = pack2(5197.5f, 5197.5f);
    const u64 C_D2 = pack2(210.0f,  210.0f);
    const u64 C_D1 = pack2(4725.0f, 4725.0f);
    const u64 C_D0 = pack2(10395.0f,10395.0f);

    const float* xrow = state + (size_t)e * (size_t)T;

    float cc   = 0.f;                     // own-unit scaled cell (-2L*c)
    float outv = 0.f;                     // own-unit hidden output
    u64 S0 = 0, S1 = 0, S2 = 0;           // duplicated s1(t-1) broadcasts
    u64 H0 = 0, H1 = 0, H2 = 0;           // duplicated h2(t-2) broadcasts

#define STEP(xv)                                                            \
    do {                                                                    \
        const u64 xp = pack2((xv), (xv));                                   \
        u64 za = ffma2(AP[0], xp, BIP[0]);   /* (i,f) args, z/2 */          \
        u64 zb = ffma2(AP[1], xp, BIP[1]);   /* (g scaled, o z/2) */        \
        za = ffma2(BP[0][0], S0, za); zb = ffma2(BP[0][1], S0, zb);         \
        za = ffma2(BP[1][0], S1, za); zb = ffma2(BP[1][1], S1, zb);         \
        za = ffma2(BP[2][0], S2, za); zb = ffma2(BP[2][1], S2, zb);         \
        za = ffma2(CP[0][0], H0, za); zb = ffma2(CP[0][1], H0, zb);         \
        za = ffma2(CP[1][0], H1, za); zb = ffma2(CP[1][1], H1, zb);         \
        za = ffma2(CP[2][0], H2, za); zb = ffma2(CP[2][1], H2, zb);         \
        /* (i,f) rational: sigma = 0.5 + num/den, num = x*N'(y), y = x^2 */ \
        const u64 y2 = fmul2(za, za);                                       \
        u64 nn = ffma2(C_N2, y2, C_N1);                                     \
        nn = ffma2(nn, y2, C_N0);                                           \
        const u64 numif = fmul2(nn, za);                                    \
        u64 dd = fadd2(y2, C_D2);                                           \
        dd = ffma2(dd, y2, C_D1);                                           \
        dd = ffma2(dd, y2, C_D0);                                           \
        float ni, nf, di, df;                                               \
        unpack2(numif, ni, nf);                                             \
        unpack2(dd, di, df);                                                \
        /* g (ex2 route) + o (scalar rational) */                           \
        float zg, zo;                                                       \
        unpack2(zb, zg, zo);                                                \
        const float eg = fast_ex2(zg);                                      \
        const float yo = zo * zo;                                           \
        float no = fmaf(10.5f, yo, 630.0f);                                 \
        no = fmaf(no, yo, 5197.5f);                                         \
        const float numo = no * zo;                                         \
        float dn = yo + 210.0f;                                             \
        dn = fmaf(dn, yo, 4725.0f);                                         \
        const float deno = fmaf(dn, yo, 10395.0f);                          \
        /* triple rcp: 1/di, 1/df, 1/dg with ONE MUFU */                    \
        const float dg  = 1.0f + eg;                                        \
        const float P   = di * df;                                          \
        const float R   = fast_rcp(P * dg);                                 \
        const float rg  = R * P;        /* 1/dg */                          \
        const float rif = R * dg;       /* 1/(di*df) */                     \
        const float ri  = rif * df;     /* 1/di */                          \
        const float rf  = rif * di;     /* 1/df */                          \
        const float si  = fmaf(ni, ri, 0.5f);                               \
        const float sf  = fmaf(nf, rf, 0.5f);                               \
        const float pp  = fmaf(2.0f * LOG2E, eg, -2.0f * LOG2E);            \
        cc = fmaf(sf, cc, si * (pp * rg));   /* cc = -2L * c */             \
        const float ec = fast_ex2(cc);                                      \
        const float dc = 1.0f + ec;                                         \
        const float Rq = fast_rcp(dc * deno);                               \
        const float t1 = Rq * deno;     /* 1/dc */                          \
        const float t2 = Rq * dc;       /* 1/deno */                        \
        const float so = fmaf(numo, t2, 0.5f);                              \
        outv = ((1.0f - ec) * t1) * so;  /* tanh(c) * sigma(o) */           \
    } while (0)

    // exchange: duplicated STS.64 into permuted slot, syncwarp, 3x LDS.128
#define XCHG(p)                                                             \
    do {                                                                    \
        xch[(p)][sslot] = pack2(outv, outv);                                \
        __syncwarp(FULLM);                                                  \
        const ulonglong2 v0 =                                               \
            *reinterpret_cast<const ulonglong2*>(&xch[(p)][gbase]);         \
        const ulonglong2 v1 =                                               \
            *reinterpret_cast<const ulonglong2*>(&xch[(p)][gbase + 2]);     \
        const ulonglong2 v2 =                                               \
            *reinterpret_cast<const ulonglong2*>(&xch[(p)][gbase + 4]);     \
        S0 = v0.x; S1 = v0.y; S2 = v1.x;                                    \
        H0 = v1.y; H1 = v2.x; H2 = v2.y;                                    \
    } while (0)

#define BODY(xv, p) do { STEP(xv); XCHG(p); } while (0)

    // ---- prologue: t = 0 (L2 lanes reset: no h2(-1)/s1(-1)), then t = 1..3
    float4 a4 = __ldg(reinterpret_cast<const float4*>(xrow));
    float4 nA = a4;
    if (T >= 8) nA = __ldg(reinterpret_cast<const float4*>(xrow + 4));

    STEP(a4.x);
    if (isL2) { cc = 0.f; outv = 0.f; }
    XCHG(0);
    BODY(a4.y, 1);
    BODY(a4.z, 0);
    BODY(a4.w, 1);

    int t = 4;
    for (; t + 7 < T; t += 4) {
        a4 = nA;
        nA = __ldg(reinterpret_cast<const float4*>(xrow + t + 4));
        BODY(a4.x, 0);
        BODY(a4.y, 1);
        BODY(a4.z, 0);
        BODY(a4.w, 1);
    }
    if (t + 3 < T) {                      // last full chunk (already prefetched)
        a4 = nA;
        BODY(a4.x, 0);
        BODY(a4.y, 1);
        BODY(a4.z, 0);
        BODY(a4.w, 1);
        t += 4;
    }
    for (; t < T; ++t) {                  // scalar tail (not taken for T=2048)
        BODY(__ldg(xrow + t), t & 1);
    }

    // ---- epilogue: one more step so L2 lanes produce h2(T-1). x unused by
    // L2 (A = 0); L1 lanes' output is never consumed.
    STEP(0.0f);
    xch[0][sslot] = pack2(outv, outv);
    __syncwarp(FULLM);

    if (lane8 == 0 && act) {
        float f0, f1, f2, junk;
        unpack2(xch[0][gbase + 3], f0, junk);   // h2 unit 0 (permuted slots)
        unpack2(xch[0][gbase + 4], f1, junk);   // h2 unit 1
        unpack2(xch[0][gbase + 5], f2, junk);   // h2 unit 2
        float r = __ldg(bd);
        r = fmaf(f0, __ldg(Wd + 0), r);
        r = fmaf(f1, __ldg(Wd + 1), r);
        r = fmaf(f2, __ldg(Wd + 2), r);
        out[e] = r;
    }

#undef STEP
#undef XCHG
#undef BODY
}

extern "C" void kernel_launch(void* const* d_in, const int* in_sizes, int n_in,
                              void* d_out, int out_size)
{
    const float* state = (const float*)d_in[0];
    const float* W1 = (const float*)d_in[1];
    const float* U1 = (const float*)d_in[2];
    const float* b1 = (const float*)d_in[3];
    const float* W2 = (const float*)d_in[4];
    const float* U2 = (const float*)d_in[5];
    const float* b2 = (const float*)d_in[6];
    const float* Wd = (const float*)d_in[7];
    const float* bd = (const float*)d_in[8];
    float* out = (float*)d_out;

    const int B = out_size;            // output is [1, B]
    const int T = in_sizes[0] / B;     // state is [B, T]

    const int elems_per_warp = 4;      // 4 groups x 8 lanes = 32
    const int blocks = (B + elems_per_warp - 1) / elems_per_warp;   // 1024
    lstm2_r16_kernel<<<blocks, 32>>>(state, W1, U1, b1, W2, U2, b2,
                                     Wd, bd, out, B, T);
}

// round 17
// speedup vs baseline: 1.2004x; 1.0448x over previous
#include <cuda_runtime.h>

// LSTMBrain: 2-layer LSTM (hidden=3) over [B=4096, T=2048], dense head 3->1.
// Round 17: R9 (champion, 313.5us) with ONE change: the serial z accumulation
// is reordered so the EXCHANGE-FRESH S-terms come LAST:
//     z = (A*x + bias) -> += C*H (one step old / zero for L1) -> += B*S
// In R9 the S-terms came first, burying them behind 6 more ffma2 (24 cyc) on
// the recurrence-critical path. Now the cycle from S-arrival is 3 ffma2 (12).
// Everything else (layout, cascade, 7 MUFU, smem exchange) is R9 verbatim.

typedef unsigned long long u64;

#define FULLM 0xFFFFFFFFu
#define LOG2E 1.4426950408889634f

__device__ __forceinline__ float fast_rcp(float x) {
    float r; asm("rcp.approx.f32 %0, %1;" : "=f"(r) : "f"(x)); return r;
}
__device__ __forceinline__ float fast_ex2(float x) {
    float r; asm("ex2.approx.f32 %0, %1;" : "=f"(r) : "f"(x)); return r;
}
__device__ __forceinline__ u64 ffma2(u64 a, u64 b, u64 c) {
    u64 d; asm("fma.rn.f32x2 %0, %1, %2, %3;" : "=l"(d) : "l"(a), "l"(b), "l"(c));
    return d;
}
__device__ __forceinline__ u64 pack2(float lo, float hi) {
    u64 d; asm("mov.b64 %0, {%1, %2};" : "=l"(d) : "f"(lo), "f"(hi)); return d;
}
__device__ __forceinline__ void unpack2(u64 v, float& lo, float& hi) {
    asm("mov.b64 {%0, %1}, %2;" : "=f"(lo), "=f"(hi) : "l"(v));
}

__global__ void __launch_bounds__(32, 1) lstm2_r17_kernel(
    const float* __restrict__ state,
    const float* __restrict__ W1, const float* __restrict__ U1, const float* __restrict__ b1,
    const float* __restrict__ W2, const float* __restrict__ U2, const float* __restrict__ b2,
    const float* __restrict__ Wd, const float* __restrict__ bd,
    float* __restrict__ out, int B, int T)
{
    __shared__ __align__(16) u64 xch[2][32];   // [buffer][slot], (v,v) dup

    const int lane  = threadIdx.x & 31;
    const int lane8 = lane & 7;
    const int gbase = lane & ~7;               // group's first lane/slot
    const int sub   = lane8 & 3;
    const int u     = (sub < 3) ? sub : 2;     // owned hidden unit (3/7 dup 2)
    const bool isL2 = (lane8 & 4) != 0;
    // permuted write slot: roles 0,1,2 -> 0,1,2 ; 4,5,6 -> 3,4,5 ; 3->6, 7->7
    const int sslot = gbase + ((lane8 < 3) ? lane8
                        : (lane8 == 3) ? 6
                        : (lane8 < 7) ? (lane8 - 1) : 7);

    int e = blockIdx.x * 4 + (lane >> 3);      // element of this group
    const bool act = (e < B);
    if (!act) e = B - 1;

    // ---- gate-pair packed coefficients, pre-scaled into the ex2 domain ----
    // pair 0 = gates (i, f)  [f-path chain-critical, computed first]
    // pair 1 = gates (g, o); column(gate) = gate*3 + u
    u64 AP[2], BIP[2], BP[3][2], CP[3][2];
#pragma unroll
    for (int pr = 0; pr < 2; ++pr) {
        const int glo = (pr == 0) ? 0 : 2;     // i or g
        const int ghi = (pr == 0) ? 1 : 3;     // f or o
        const int clo = glo * 3 + u, chi = ghi * 3 + u;
        const float slo = (glo == 2) ? (-2.0f * LOG2E) : (-LOG2E);
        const float shi = -LOG2E;
        if (isL2) {
            AP[pr]  = 0;
            BIP[pr] = pack2(__ldg(b2 + clo) * slo, __ldg(b2 + chi) * shi);
#pragma unroll
            for (int k = 0; k < 3; ++k) {
                BP[k][pr] = pack2(__ldg(W2 + k * 12 + clo) * slo,
                                  __ldg(W2 + k * 12 + chi) * shi);  // * s1 (fresh)
                CP[k][pr] = pack2(__ldg(U2 + k * 12 + clo) * slo,
                                  __ldg(U2 + k * 12 + chi) * shi);  // * h2 (old)
            }
        } else {
            AP[pr]  = pack2(__ldg(W1 + clo) * slo, __ldg(W1 + chi) * shi);
            BIP[pr] = pack2(__ldg(b1 + clo) * slo, __ldg(b1 + chi) * shi);
#pragma unroll
            for (int k = 0; k < 3; ++k) {
                BP[k][pr] = pack2(__ldg(U1 + k * 12 + clo) * slo,
                                  __ldg(U1 + k * 12 + chi) * shi);  // * s1 (fresh)
                CP[k][pr] = 0;
            }
        }
    }

    const float* xrow = state + (size_t)e * (size_t)T;

    float cc   = 0.f;                     // own-unit scaled cell state
    float outv = 0.f;                     // own-unit hidden output
    u64 S0 = 0, S1 = 0, S2 = 0;           // duplicated s1(t-1) broadcasts (FRESH)
    u64 H0 = 0, H1 = 0, H2 = 0;           // duplicated h2(t-2) broadcasts (OLD)

    // STEP: z accumulated x/bias -> H-terms -> S-terms LAST (chain cut);
    // cascade identical to R9 (7 MUFU: 4 gate ex2 + cell ex2 + 2 rcp).
#define STEP(xv)                                                            \
    do {                                                                    \
        const u64 xp = pack2((xv), (xv));                                   \
        u64 za = ffma2(AP[0], xp, BIP[0]);                                  \
        u64 zb = ffma2(AP[1], xp, BIP[1]);                                  \
        za = ffma2(CP[0][0], H0, za); zb = ffma2(CP[0][1], H0, zb);         \
        za = ffma2(CP[1][0], H1, za); zb = ffma2(CP[1][1], H1, zb);         \
        za = ffma2(CP[2][0], H2, za); zb = ffma2(CP[2][1], H2, zb);         \
        za = ffma2(BP[0][0], S0, za); zb = ffma2(BP[0][1], S0, zb);         \
        za = ffma2(BP[1][0], S1, za); zb = ffma2(BP[1][1], S1, zb);         \
        za = ffma2(BP[2][0], S2, za); zb = ffma2(BP[2][1], S2, zb);         \
        float zi, zf, zg, zo;                                               \
        unpack2(za, zi, zf); unpack2(zb, zg, zo);                           \
        const float ei = fast_ex2(zi);                                      \
        const float ef = fast_ex2(zf);                                      \
        const float eg = fast_ex2(zg);                                      \
        const float eo = fast_ex2(zo);                                      \
        const float di = 1.0f + ei, df = 1.0f + ef;                         \
        const float dg = 1.0f + eg, dq = 1.0f + eo;                         \
        const float m1 = di * dg;                                           \
        const float Rm = fast_rcp(m1 * df);                                 \
        const float sf  = Rm * m1;    /* 1/df */                            \
        const float r02 = Rm * df;    /* 1/(di*dg) */                       \
        const float pp  = fmaf(2.0f * LOG2E, eg, -2.0f * LOG2E);            \
        cc = fmaf(sf, cc, pp * r02);                                        \
        const float ec = fast_ex2(cc);                                      \
        const float dc = 1.0f + ec;                                         \
        const float Rq = fast_rcp(dc * dq);                                 \
        outv = (1.0f - ec) * Rq;      /* tanh(c) * sigmoid(o) */            \
    } while (0)

    // exchange: duplicated STS.64 into permuted slot, syncwarp, 3x LDS.128
#define XCHG(p)                                                             \
    do {                                                                    \
        xch[(p)][sslot] = pack2(outv, outv);                                \
        __syncwarp(FULLM);                                                  \
        const ulonglong2 v0 =                                               \
            *reinterpret_cast<const ulonglong2*>(&xch[(p)][gbase]);         \
        const ulonglong2 v1 =                                               \
            *reinterpret_cast<const ulonglong2*>(&xch[(p)][gbase + 2]);     \
        const ulonglong2 v2 =                                               \
            *reinterpret_cast<const ulonglong2*>(&xch[(p)][gbase + 4]);     \
        S0 = v0.x; S1 = v0.y; S2 = v1.x;                                    \
        H0 = v1.y; H1 = v2.x; H2 = v2.y;                                    \
    } while (0)

#define BODY(xv, p) do { STEP(xv); XCHG(p); } while (0)

    // ---- prologue: t = 0 (L2 lanes reset: no h2(-1)/s1(-1)), then t = 1..3
    float4 a4 = __ldg(reinterpret_cast<const float4*>(xrow));
    float4 nA = a4;
    if (T >= 8) nA = __ldg(reinterpret_cast<const float4*>(xrow + 4));

    STEP(a4.x);
    if (isL2) { cc = 0.f; outv = 0.f; }
    XCHG(0);
    BODY(a4.y, 1);
    BODY(a4.z, 0);
    BODY(a4.w, 1);

    int t = 4;
    for (; t + 7 < T; t += 4) {
        a4 = nA;
        nA = __ldg(reinterpret_cast<const float4*>(xrow + t + 4));
        BODY(a4.x, 0);
        BODY(a4.y, 1);
        BODY(a4.z, 0);
        BODY(a4.w, 1);
    }
    if (t + 3 < T) {                      // last full chunk (already prefetched)
        a4 = nA;
        BODY(a4.x, 0);
        BODY(a4.y, 1);
        BODY(a4.z, 0);
        BODY(a4.w, 1);
        t += 4;
    }
    for (; t < T; ++t) {                  // scalar tail (not taken for T=2048)
        BODY(__ldg(xrow + t), t & 1);
    }

    // ---- epilogue: one more step so L2 lanes produce h2(T-1). x unused by
    // L2 (A = 0); L1 lanes' output is never consumed.
    STEP(0.0f);
    xch[0][sslot] = pack2(outv, outv);
    __syncwarp(FULLM);

    if (lane8 == 0 && act) {
        float f0, f1, f2, junk;
        unpack2(xch[0][gbase + 3], f0, junk);   // h2 unit 0 (permuted slots)
        unpack2(xch[0][gbase + 4], f1, junk);   // h2 unit 1
        unpack2(xch[0][gbase + 5], f2, junk);   // h2 unit 2
        float r = __ldg(bd);
        r = fmaf(f0, __ldg(Wd + 0), r);
        r = fmaf(f1, __ldg(Wd + 1), r);
        r = fmaf(f2, __ldg(Wd + 2), r);
        out[e] = r;
    }

#undef STEP
#undef XCHG
#undef BODY
}

extern "C" void kernel_launch(void* const* d_in, const int* in_sizes, int n_in,
                              void* d_out, int out_size)
{
    const float* state = (const float*)d_in[0];
    const float* W1 = (const float*)d_in[1];
    const float* U1 = (const float*)d_in[2];
    const float* b1 = (const float*)d_in[3];
    const float* W2 = (const float*)d_in[4];
    const float* U2 = (const float*)d_in[5];
    const float* b2 = (const float*)d_in[6];
    const float* Wd = (const float*)d_in[7];
    const float* bd = (const float*)d_in[8];
    float* out = (float*)d_out;

    const int B = out_size;            // output is [1, B]
    const int T = in_sizes[0] / B;     // state is [B, T]

    const int elems_per_warp = 4;      // 4 groups x 8 lanes = 32
    const int blocks = (B + elems_per_warp - 1) / elems_per_warp;   // 1024
    lstm2_r17_kernel<<<blocks, 32>>>(state, W1, U1, b1, W2, U2, b2,
                                     Wd, bd, out, B, T);
}